// round 14
// baseline (speedup 1.0000x reference)
#include <cuda_runtime.h>
#include <math.h>

namespace {
constexpr int B_   = 32;
constexpr int S_   = 1024;
constexpr int D_   = 512;
constexpr int H_   = 4;
constexpr int DH_  = 384;
constexpr int FFN_ = 2048;
constexpr int NCH_ = 4;     // 256-row chunks for alpha/y -> 128 tiles (1 wave)
constexpr int NB_  = 148;   // one block per SM — all resident
constexpr int NT_  = 512;
}

// ---------------- static scratch ----------------
__device__ float g_Pos[S_ * D_];                  // 2 MB
__device__ float g_x0[B_ * D_];
__device__ float g_w[B_ * H_ * D_];
__device__ float g_c[B_ * H_];
__device__ float g_ypart[B_ * NCH_ * H_ * D_];    // 1 MB
__device__ float g_Apart[B_ * NCH_ * H_];
__device__ float g_hp[16][B_ * D_];               // F1 partials
__device__ float g_x1p[16][B_ * D_];              // F2 partials
__device__ float g_x1n[B_ * D_];                  // post-LN1
__device__ float g_h1p[8][B_ * FFN_];             // F3 partials
__device__ float g_x2p[32][B_ * D_];              // F4 partials
__device__ float g_x2[B_ * D_];                   // post-LN2
__device__ float g_hidp[16][B_ * D_];             // F5 partials

// ---------------- grid barrier (flat — measured cheap) ----------------
__device__ unsigned g_cnt = 0;
__device__ volatile unsigned g_gen = 0;

__device__ __forceinline__ void grid_bar() {
    __syncthreads();
    if (threadIdx.x == 0) {
        unsigned gen = g_gen;               // read BEFORE arriving
        __threadfence();                    // release
        if (atomicAdd(&g_cnt, 1u) == NB_ - 1u) {
            g_cnt = 0;
            __threadfence();
            g_gen = gen + 1u;
        } else {
            while (g_gen == gen) __nanosleep(64);
        }
        __threadfence();                    // acquire
    }
    __syncthreads();
}

// ---------------- shared memory union (dynamic) ----------------
struct SA { float xs[3][16][512]; float al[2][16][4]; };   // 96.5 KB
struct SG { float As[32][64]; };
struct SQ { float x0s[512]; float q0p[512]; float q0s[128]; float red[32]; };
struct SR { float red[32]; };
union  SM { SA a; SG g; SQ q; SR r; };

// block reduction over 512 threads: warp shuffle + cross-warp shuffle
__device__ __forceinline__ float redsum(float v, float* red) {
    int tid = threadIdx.x;
    int lane = tid & 31, w = tid >> 5;
#pragma unroll
    for (int off = 16; off > 0; off >>= 1)
        v += __shfl_xor_sync(0xffffffff, v, off);
    if (lane == 0) red[w] = v;
    __syncthreads();
    float r = red[lane & 15];
    if (w == 0) {
#pragma unroll
        for (int off = 8; off > 0; off >>= 1)
            r += __shfl_xor_sync(0xffffffff, r, off);
        if (lane == 0) red[0] = r;
    }
    __syncthreads();
    r = red[0];
    __syncthreads();   // protect red for next call
    return r;
}

// 128-col tiles: C[32, NCT*128] += A[32, NKT*64] @ W (F3/F4)
#define GEMM_TILE(NCT, NKT, STAGE_EXPR, INIT_STMT, WADDR_EXPR, OUT_STMT)        \
  if (blk < (NCT) * (NKT)) {                                                    \
    const int ct = blk / (NKT), kb = blk % (NKT);                               \
    const int col = ct * 128 + cg * 4;  (void)col;                              \
    _Pragma("unroll")                                                           \
    for (int r = 0; r < 4; r++) {                                               \
      int idx = tid + NT_ * r;                                                  \
      int bb = idx >> 6, kk = idx & 63;                                         \
      int kg = kb * 64 + kk;  (void)kg;                                         \
      sm.g.As[bb][kk] = (STAGE_EXPR);                                           \
    }                                                                           \
    __syncthreads();                                                            \
    float4 acc[2];                                                              \
    INIT_STMT;                                                                  \
    _Pragma("unroll 8")                                                         \
    for (int k = 0; k < 64; k++) {                                              \
      int kg = kb * 64 + k;                                                     \
      float4 wv = *(const float4*)(WADDR_EXPR);                                 \
      _Pragma("unroll")                                                         \
      for (int j = 0; j < 2; j++) {                                             \
        float a = sm.g.As[bg * 2 + j][k];                                       \
        acc[j].x += a * wv.x; acc[j].y += a * wv.y;                             \
        acc[j].z += a * wv.z; acc[j].w += a * wv.w;                             \
      }                                                                         \
    }                                                                           \
    OUT_STMT;                                                                   \
    __syncthreads();                                                            \
  }

// 64-col tiles, 128 blocks: 8 col-tiles x 16 K-splits (slice 32), 1 batch/thread.
#define GEMM_TILE64(STAGE_EXPR, INIT_STMT, WADDR_EXPR, OUT_STMT)                \
  if (blk < 128) {                                                              \
    const int ct = blk >> 4, kb = blk & 15;                                     \
    const int cg16 = tid & 15, bb1 = tid >> 4;                                  \
    const int col = ct * 64 + cg16 * 4;  (void)col; (void)bb1;                  \
    _Pragma("unroll")                                                           \
    for (int r = 0; r < 2; r++) {                                               \
      int idx = tid + NT_ * r;                                                  \
      int bb = idx >> 5, kk = idx & 31;                                         \
      int kg = kb * 32 + kk;  (void)kg;                                         \
      sm.g.As[bb][kk] = (STAGE_EXPR);                                           \
    }                                                                           \
    __syncthreads();                                                            \
    float4 acc;                                                                 \
    INIT_STMT;                                                                  \
    _Pragma("unroll 8")                                                         \
    for (int k = 0; k < 32; k++) {                                              \
      int kg = kb * 32 + k;                                                     \
      float4 wv = *(const float4*)(WADDR_EXPR);                                 \
      float a = sm.g.As[bb1][k];                                                \
      acc.x += a * wv.x; acc.y += a * wv.y;                                     \
      acc.z += a * wv.z; acc.w += a * wv.w;                                     \
    }                                                                           \
    OUT_STMT;                                                                   \
    __syncthreads();                                                            \
  }

#define ACC_ZERO() do {                                                         \
    acc[0] = make_float4(0.f, 0.f, 0.f, 0.f);                                   \
    acc[1] = make_float4(0.f, 0.f, 0.f, 0.f); } while (0)

__global__ __launch_bounds__(NT_, 1) void mega_kernel(
    const int*   __restrict__ tok,  const float* __restrict__ emb,
    const float* __restrict__ Wp,   const float* __restrict__ bp,
    const float* __restrict__ Wo,   const float* __restrict__ bo,
    const float* __restrict__ g1,   const float* __restrict__ bln1,
    const float* __restrict__ W1,   const float* __restrict__ b1,
    const float* __restrict__ W2,   const float* __restrict__ b2,
    const float* __restrict__ g2,   const float* __restrict__ bln2,
    const float* __restrict__ Wh,   const float* __restrict__ bhw,
    const float* __restrict__ Wf,   const float* __restrict__ bf,
    float* __restrict__ out, int out_size)
{
    extern __shared__ __align__(16) char smem_raw[];
    SM& sm = *reinterpret_cast<SM*>(smem_raw);
    const int blk = blockIdx.x;
    const int tid = threadIdx.x;
    const int lane = tid & 31, wid = tid >> 5;
    const int cg = lane, bg = wid;

    // ========== Stage 1: pos table (ALL blocks) + qw (blk<128) ==========
    // stride NB*NT is a multiple of 512 -> i (and freq) loop-invariant per thread
    {
        int idx0 = blk * NT_ + tid;
        int i = idx0 & 511;
        // 10000^(-2*(i/2)/512) = exp2(-2*log2(10000)/512 * (i/2))
        float freq = exp2f(-0.05190512648261504f * (float)(i >> 1));
        bool isOdd = (i & 1);
        for (int idx = idx0; idx < S_ * D_; idx += NB_ * NT_) {
            int t = idx >> 9;
            float ang = (float)t * freq;
            g_Pos[idx] = isOdd ? cosf(ang) : sinf(ang);
        }
    }
    if (blk < 128) {
        int b = blk >> 2, qt = blk & 3;
        int t0 = tok[b * S_];
        float v = emb[(size_t)t0 * D_ + tid] + (float)(tid & 1);
        sm.q.x0s[tid] = v;
        if (qt == 0) g_x0[b * D_ + tid] = v;
        __syncthreads();

        {   // q0[qt][e] partials: 4 threads per e, quarter-split over d
            int quarter = tid >> 7, e = tid & 127;
            const float* wp = Wp + ((size_t)qt * D_ + quarter * 128) * DH_ + e;
            const float* xq = sm.q.x0s + quarter * 128;
            float a0 = 0.f, a1 = 0.f, a2 = 0.f, a3 = 0.f;
#pragma unroll 8
            for (int d = 0; d < 128; d += 4) {
                a0 += xq[d + 0] * wp[(size_t)(d + 0) * DH_];
                a1 += xq[d + 1] * wp[(size_t)(d + 1) * DH_];
                a2 += xq[d + 2] * wp[(size_t)(d + 2) * DH_];
                a3 += xq[d + 3] * wp[(size_t)(d + 3) * DH_];
            }
            sm.q.q0p[quarter * 128 + e] = (a0 + a1) + (a2 + a3);
        }
        __syncthreads();

        if (tid < 128) {
            float q = bp[qt * DH_ + tid] +
                      ((sm.q.q0p[tid] + sm.q.q0p[128 + tid]) +
                       (sm.q.q0p[256 + tid] + sm.q.q0p[384 + tid]));
            sm.q.q0s[tid] = q;
            // c contribution: q0 . bk
            float val = q * bp[qt * DH_ + 128 + tid];
#pragma unroll
            for (int off = 16; off > 0; off >>= 1)
                val += __shfl_xor_sync(0xffffffff, val, off);
            if (lane == 0) sm.q.red[wid] = val;   // wid 0..3
        }
        __syncthreads();
        if (tid == 0)
            g_c[b * H_ + qt] = (sm.q.red[0] + sm.q.red[1]) +
                               (sm.q.red[2] + sm.q.red[3]);

        {   // w for head qt, d = tid (reads Wk[qt] slab, coalesced over e)
            const float4* wp4 = (const float4*)(Wp + ((size_t)qt * D_ + tid) * DH_ + 128);
            const float4* q4  = (const float4*)(sm.q.q0s);
            float acc = 0.f;
#pragma unroll
            for (int e4 = 0; e4 < 32; e4++) {
                float4 wv = wp4[e4], qv = q4[e4];
                acc += wv.x * qv.x + wv.y * qv.y + wv.z * qv.z + wv.w * qv.w;
            }
            g_w[b * (H_ * D_) + qt * D_ + tid] = acc;
        }
    }
    grid_bar();

    // ========== Stage C: pipelined gather + alpha + y (128 tiles, 1 sync/iter) ==========
    if (blk < B_ * NCH_) {
        const int b = blk & 31, chunk = blk >> 5;
        const float4* emb4 = (const float4*)emb;
        const float4* pos4 = (const float4*)g_Pos;

        // w cached in registers: wr[h][k] covers f4-group (lane + 32k)
        float4 wr[4][4];
        {
            const float4* gw4 = (const float4*)(g_w + b * (H_ * D_));
#pragma unroll
            for (int h = 0; h < 4; h++)
#pragma unroll
                for (int k = 0; k < 4; k++)
                    wr[h][k] = gw4[h * 128 + lane + 32 * k];
        }
        const float cs0 = g_c[b * H_ + 0];
        const float cs1 = g_c[b * H_ + 1];
        const float cs2 = g_c[b * H_ + 2];
        const float cs3 = g_c[b * H_ + 3];

        const int prow = tid >> 7, pc4 = tid & 127;
        float4 ev[4], pv[4];

        {   // prologue: issue loads for subtile 0
            int r0 = chunk * 256;
#pragma unroll
            for (int r = 0; r < 4; r++) {
                int row = prow + r * 4;
                int tk = tok[b * S_ + r0 + row];
                ev[r] = emb4[(size_t)tk * 128 + pc4];
                pv[r] = pos4[(size_t)(r0 + row) * 128 + pc4];
            }
        }

        float y0 = 0.f, y1 = 0.f, y2 = 0.f, y3 = 0.f;
        float aw0 = 0.f, aw1 = 0.f, aw2 = 0.f, aw3 = 0.f;   // per-warp A accum (lane0)

        for (int sub = 0; sub <= 16; sub++) {
            if (sub < 16) {
                // store prefetched subtile into xs[sub%3]
                float4* xst = (float4*)sm.a.xs[sub % 3];
#pragma unroll
                for (int r = 0; r < 4; r++) {
                    float4 vv;
                    vv.x = ev[r].x + pv[r].x; vv.y = ev[r].y + pv[r].y;
                    vv.z = ev[r].z + pv[r].z; vv.w = ev[r].w + pv[r].w;
                    xst[(prow + r * 4) * 128 + pc4] = vv;
                }
                if (sub < 15) {
                    int r0 = chunk * 256 + (sub + 1) * 16;
#pragma unroll
                    for (int r = 0; r < 4; r++) {
                        int row = prow + r * 4;
                        int tk = tok[b * S_ + r0 + row];
                        ev[r] = emb4[(size_t)tk * 128 + pc4];
                        pv[r] = pos4[(size_t)(r0 + row) * 128 + pc4];
                    }
                }
            }
            __syncthreads();

            if (sub < 16) {
                // alpha(sub): 16 warps, one row each; w from registers
                const float4* xr = (const float4*)&sm.a.xs[sub % 3][wid][0];
                float s0 = 0.f, s1 = 0.f, s2 = 0.f, s3 = 0.f;
#pragma unroll
                for (int k = 0; k < 4; k++) {
                    float4 xv = xr[lane + 32 * k];
                    s0 += xv.x * wr[0][k].x + xv.y * wr[0][k].y
                        + xv.z * wr[0][k].z + xv.w * wr[0][k].w;
                    s1 += xv.x * wr[1][k].x + xv.y * wr[1][k].y
                        + xv.z * wr[1][k].z + xv.w * wr[1][k].w;
                    s2 += xv.x * wr[2][k].x + xv.y * wr[2][k].y
                        + xv.z * wr[2][k].z + xv.w * wr[2][k].w;
                    s3 += xv.x * wr[3][k].x + xv.y * wr[3][k].y
                        + xv.z * wr[3][k].z + xv.w * wr[3][k].w;
                }
#pragma unroll
                for (int off = 16; off > 0; off >>= 1) {
                    s0 += __shfl_xor_sync(0xffffffff, s0, off);
                    s1 += __shfl_xor_sync(0xffffffff, s1, off);
                    s2 += __shfl_xor_sync(0xffffffff, s2, off);
                    s3 += __shfl_xor_sync(0xffffffff, s3, off);
                }
                if (lane == 0) {
                    float a0 = s0 + cs0, a1 = s1 + cs1, a2 = s2 + cs2, a3 = s3 + cs3;
                    sm.a.al[sub & 1][wid][0] = a0;
                    sm.a.al[sub & 1][wid][1] = a1;
                    sm.a.al[sub & 1][wid][2] = a2;
                    sm.a.al[sub & 1][wid][3] = a3;
                    aw0 += a0; aw1 += a1; aw2 += a2; aw3 += a3;
                }
            }
            if (sub >= 1) {
                // y accumulation for subtile sub-1 (al written last iter, xs 2 bufs back)
                int ps = sub - 1;
                const float (*alp)[4] = sm.a.al[ps & 1];
                const float (*xsp)[512] = sm.a.xs[ps % 3];
#pragma unroll
                for (int tt = 0; tt < 16; tt++) {
                    float xv = xsp[tt][tid];
                    float4 a4 = *(const float4*)&alp[tt][0];
                    y0 += a4.x * xv;
                    y1 += a4.y * xv;
                    y2 += a4.z * xv;
                    y3 += a4.w * xv;
                }
            }
        }

        float* yp = g_ypart + ((size_t)(b * NCH_ + chunk)) * (H_ * D_);
        yp[0 * D_ + tid] = y0;
        yp[1 * D_ + tid] = y1;
        yp[2 * D_ + tid] = y2;
        yp[3 * D_ + tid] = y3;

        // A reduction: lane0s deposit per-warp sums, 4 threads reduce across warps
        if (lane == 0) {
            sm.a.al[0][wid][0] = aw0;
            sm.a.al[0][wid][1] = aw1;
            sm.a.al[0][wid][2] = aw2;
            sm.a.al[0][wid][3] = aw3;
        }
        __syncthreads();
        if (tid < H_) {
            float a = 0.f;
#pragma unroll
            for (int w = 0; w < 16; w++) a += sm.a.al[0][w][tid];
            g_Apart[(b * NCH_ + chunk) * H_ + tid] = a;
        }
        __syncthreads();
    }
    grid_bar();

    // ========== F1: heads = y @ Wv + A*bv  (128 tiles of 64 cols) ==========
    GEMM_TILE64(
        /*stage*/ ({
            const int h_ = ct >> 1;
            float s = 0.f;
            _Pragma("unroll")
            for (int c = 0; c < NCH_; c++)
                s += g_ypart[((size_t)(bb * NCH_ + c)) * (H_ * D_) + h_ * D_ + kg];
            s; }),
        /*init*/ do {
            if (kb == 0) {
                const int h_ = ct >> 1;
                float4 bv = *(const float4*)&bp[h_ * DH_ + 256 + (ct & 1) * 64 + cg16 * 4];
                float av = 0.f;
                _Pragma("unroll")
                for (int c = 0; c < NCH_; c++) av += g_Apart[(bb1 * NCH_ + c) * H_ + h_];
                acc.x = av * bv.x; acc.y = av * bv.y;
                acc.z = av * bv.z; acc.w = av * bv.w;
            } else acc = make_float4(0.f, 0.f, 0.f, 0.f);
        } while (0),
        /*W*/ (Wp + ((size_t)(ct >> 1) * D_ + kg) * DH_ + 256 + (ct & 1) * 64 + cg16 * 4),
        /*out*/ do { *(float4*)&g_hp[kb][bb1 * D_ + col] = acc; } while (0));
    grid_bar();

    // ========== F2: x1 = scale*heads @ Wo + bo + x0  (128 tiles) ==========
    GEMM_TILE64(
        /*stage*/ ({
            float s = 0.f;
            _Pragma("unroll")
            for (int p = 0; p < 16; p++) s += g_hp[p][bb * D_ + kg];
            s * 0.03125f; }),
        /*init*/ do {
            if (kb == 0) {
                float4 bv = *(const float4*)&bo[col];
                float4 xv = *(const float4*)&g_x0[bb1 * D_ + col];
                acc.x = bv.x + xv.x; acc.y = bv.y + xv.y;
                acc.z = bv.z + xv.z; acc.w = bv.w + xv.w;
            } else acc = make_float4(0.f, 0.f, 0.f, 0.f);
        } while (0),
        /*W*/ (Wo + (size_t)kg * D_ + col),
        /*out*/ do { *(float4*)&g_x1p[kb][bb1 * D_ + col] = acc; } while (0));
    grid_bar();

    // ========== LN1 ==========
    if (blk < B_) {
        int b = blk;
        float v = 0.f;
#pragma unroll
        for (int p = 0; p < 16; p++) v += g_x1p[p][b * D_ + tid];
        float mu  = redsum(v, sm.r.red) * (1.f / D_);
        float dv  = v - mu;
        float var = redsum(dv * dv, sm.r.red) * (1.f / D_);
        g_x1n[b * D_ + tid] = dv * rsqrtf(var + 1e-3f) * g1[tid] + bln1[tid];
    }
    grid_bar();

    // ========== F3: h1 = x1n @ W1 + b1  (128 tiles) ==========
    GEMM_TILE(16, 8,
        /*stage*/ (g_x1n[bb * D_ + kg]),
        /*init*/ do {
            if (kb == 0) {
                float4 bv = *(const float4*)&b1[col];
                acc[0] = bv; acc[1] = bv;
            } else ACC_ZERO();
        } while (0),
        /*W*/ (W1 + (size_t)kg * FFN_ + col),
        /*out*/ do {
            _Pragma("unroll")
            for (int j = 0; j < 2; j++)
                *(float4*)&g_h1p[kb][(bg * 2 + j) * FFN_ + col] = acc[j];
        } while (0));
    grid_bar();

    // ========== F4: x2 = relu(h1) @ W2 + b2 + x1n  (128 tiles) ==========
    GEMM_TILE(4, 32,
        /*stage*/ ({
            float s = 0.f;
            _Pragma("unroll")
            for (int p = 0; p < 8; p++) s += g_h1p[p][bb * FFN_ + kg];
            fmaxf(s, 0.f); }),
        /*init*/ do {
            if (kb == 0) {
                float4 bv = *(const float4*)&b2[col];
                _Pragma("unroll")
                for (int j = 0; j < 2; j++) {
                    float4 xv = *(const float4*)&g_x1n[(bg * 2 + j) * D_ + col];
                    acc[j].x = bv.x + xv.x; acc[j].y = bv.y + xv.y;
                    acc[j].z = bv.z + xv.z; acc[j].w = bv.w + xv.w;
                }
            } else ACC_ZERO();
        } while (0),
        /*W*/ (W2 + (size_t)kg * D_ + col),
        /*out*/ do {
            _Pragma("unroll")
            for (int j = 0; j < 2; j++)
                *(float4*)&g_x2p[kb][(bg * 2 + j) * D_ + col] = acc[j];
        } while (0));
    grid_bar();

    // ========== LN2 ==========
    if (blk < B_) {
        int b = blk;
        float v = 0.f;
#pragma unroll
        for (int p = 0; p < 32; p++) v += g_x2p[p][b * D_ + tid];
        float mu  = redsum(v, sm.r.red) * (1.f / D_);
        float dv  = v - mu;
        float var = redsum(dv * dv, sm.r.red) * (1.f / D_);
        g_x2[b * D_ + tid] = dv * rsqrtf(var + 1e-3f) * g2[tid] + bln2[tid];
    }
    grid_bar();

    // ========== F5: hid = x2 @ Wh + bh  (128 tiles) ==========
    GEMM_TILE64(
        /*stage*/ (g_x2[bb * D_ + kg]),
        /*init*/ do {
            if (kb == 0) {
                acc = *(const float4*)&bhw[col];
            } else acc = make_float4(0.f, 0.f, 0.f, 0.f);
        } while (0),
        /*W*/ (Wh + (size_t)kg * D_ + col),
        /*out*/ do { *(float4*)&g_hidp[kb][bb1 * D_ + col] = acc; } while (0));
    grid_bar();

    // ========== logits ==========
    if (blk < B_) {
        int b = blk;
        float v = 0.f;
#pragma unroll
        for (int p = 0; p < 16; p++) v += g_hidp[p][b * D_ + tid];
        float hid = fmaxf(v, 0.f);
        float s = redsum(hid * Wf[tid], sm.r.red);
        if (tid == 0) {
            float logit = s + bf[0];
            if (b < out_size)      out[b]      = logit;
            if (B_ + b < out_size) out[B_ + b] = 1.f / (1.f + expf(-logit));
        }
    }
}

// ---------------------------------------------------------------------------
extern "C" void kernel_launch(void* const* d_in, const int* in_sizes, int n_in,
                              void* d_out, int out_size) {
    const int*   inputs = (const int*)  d_in[0];
    const float* emb    = (const float*)d_in[1];
    const float* Wp     = (const float*)d_in[2];
    const float* bp     = (const float*)d_in[3];
    const float* Wo     = (const float*)d_in[4];
    const float* bo     = (const float*)d_in[5];
    const float* ln1g   = (const float*)d_in[6];
    const float* ln1b   = (const float*)d_in[7];
    const float* W1     = (const float*)d_in[8];
    const float* b1     = (const float*)d_in[9];
    const float* W2     = (const float*)d_in[10];
    const float* b2     = (const float*)d_in[11];
    const float* ln2g   = (const float*)d_in[12];
    const float* ln2b   = (const float*)d_in[13];
    const float* Wh     = (const float*)d_in[14];
    const float* bhp    = (const float*)d_in[15];
    const float* Wf     = (const float*)d_in[16];
    const float* bf     = (const float*)d_in[17];
    float* out = (float*)d_out;

    static_assert(sizeof(SM) < 200 * 1024, "smem budget");
    cudaFuncSetAttribute(mega_kernel,
                         cudaFuncAttributeMaxDynamicSharedMemorySize,
                         (int)sizeof(SM));
    mega_kernel<<<NB_, NT_, sizeof(SM)>>>(inputs, emb, Wp, bp, Wo, bo,
                                          ln1g, ln1b, W1, b1, W2, b2,
                                          ln2g, ln2b, Wh, bhp, Wf, bf,
                                          out, out_size);
}

// round 15
// speedup vs baseline: 1.3879x; 1.3879x over previous
#include <cuda_runtime.h>
#include <math.h>

namespace {
constexpr int B_   = 32;
constexpr int S_   = 1024;
constexpr int D_   = 512;
constexpr int H_   = 4;
constexpr int DH_  = 384;
constexpr int FFN_ = 2048;
constexpr int NCH_ = 4;     // 256-row chunks for alpha/y -> 128 tiles (1 wave)
constexpr int NB_  = 148;   // one block per SM — all resident
constexpr int NT_  = 512;
}

// ---------------- static scratch ----------------
__device__ float g_Pos[S_ * D_];                  // 2 MB
__device__ float g_x0[B_ * D_];
__device__ float g_w[B_ * H_ * D_];
__device__ float g_c[B_ * H_];
__device__ float g_ypart[B_ * NCH_ * H_ * D_];    // 1 MB
__device__ float g_Apart[B_ * NCH_ * H_];
__device__ float g_hp[16][B_ * D_];               // F1 partials
__device__ float g_x1p[16][B_ * D_];              // F2 partials
__device__ float g_x1n[B_ * D_];                  // post-LN1
__device__ float g_h1p[8][B_ * FFN_];             // F3 partials
__device__ float g_x2p[32][B_ * D_];              // F4 partials
__device__ float g_x2[B_ * D_];                   // post-LN2
__device__ float g_hidp[16][B_ * D_];             // F5 partials

// ---------------- grid barrier (flat — measured cheap) ----------------
__device__ unsigned g_cnt = 0;
__device__ volatile unsigned g_gen = 0;

__device__ __forceinline__ void grid_bar() {
    __syncthreads();
    if (threadIdx.x == 0) {
        unsigned gen = g_gen;               // read BEFORE arriving
        __threadfence();                    // release
        if (atomicAdd(&g_cnt, 1u) == NB_ - 1u) {
            g_cnt = 0;
            __threadfence();
            g_gen = gen + 1u;
        } else {
            while (g_gen == gen) __nanosleep(64);
        }
        __threadfence();                    // acquire
    }
    __syncthreads();
}

// ---------------- shared memory union (dynamic) ----------------
struct SA { float xs[3][16][512]; float al[2][16][4]; };   // 96.5 KB
struct SG { float As[32][64]; };
struct SQ { float x0s[512]; float q0s[512]; };
struct SR { float red[32]; };
union  SM { SA a; SG g; SQ q; SR r; };

// block reduction over 512 threads: warp shuffle + cross-warp shuffle
__device__ __forceinline__ float redsum(float v, float* red) {
    int tid = threadIdx.x;
    int lane = tid & 31, w = tid >> 5;
#pragma unroll
    for (int off = 16; off > 0; off >>= 1)
        v += __shfl_xor_sync(0xffffffff, v, off);
    if (lane == 0) red[w] = v;
    __syncthreads();
    float r = red[lane & 15];
    if (w == 0) {
#pragma unroll
        for (int off = 8; off > 0; off >>= 1)
            r += __shfl_xor_sync(0xffffffff, r, off);
        if (lane == 0) red[0] = r;
    }
    __syncthreads();
    r = red[0];
    __syncthreads();   // protect red for next call
    return r;
}

// 128-col tiles: C[32, NCT*128] += A[32, NKT*64] @ W (F3/F4)
#define GEMM_TILE(NCT, NKT, STAGE_EXPR, INIT_STMT, WADDR_EXPR, OUT_STMT)        \
  if (blk < (NCT) * (NKT)) {                                                    \
    const int ct = blk / (NKT), kb = blk % (NKT);                               \
    const int col = ct * 128 + cg * 4;  (void)col;                              \
    _Pragma("unroll")                                                           \
    for (int r = 0; r < 4; r++) {                                               \
      int idx = tid + NT_ * r;                                                  \
      int bb = idx >> 6, kk = idx & 63;                                         \
      int kg = kb * 64 + kk;  (void)kg;                                         \
      sm.g.As[bb][kk] = (STAGE_EXPR);                                           \
    }                                                                           \
    __syncthreads();                                                            \
    float4 acc[2];                                                              \
    INIT_STMT;                                                                  \
    _Pragma("unroll 8")                                                         \
    for (int k = 0; k < 64; k++) {                                              \
      int kg = kb * 64 + k;                                                     \
      float4 wv = *(const float4*)(WADDR_EXPR);                                 \
      _Pragma("unroll")                                                         \
      for (int j = 0; j < 2; j++) {                                             \
        float a = sm.g.As[bg * 2 + j][k];                                       \
        acc[j].x += a * wv.x; acc[j].y += a * wv.y;                             \
        acc[j].z += a * wv.z; acc[j].w += a * wv.w;                             \
      }                                                                         \
    }                                                                           \
    OUT_STMT;                                                                   \
    __syncthreads();                                                            \
  }

// 64-col tiles, 128 blocks: 8 col-tiles x 16 K-splits (slice 32), 1 batch/thread.
#define GEMM_TILE64(STAGE_EXPR, INIT_STMT, WADDR_EXPR, OUT_STMT)                \
  if (blk < 128) {                                                              \
    const int ct = blk >> 4, kb = blk & 15;                                     \
    const int cg16 = tid & 15, bb1 = tid >> 4;                                  \
    const int col = ct * 64 + cg16 * 4;  (void)col; (void)bb1;                  \
    _Pragma("unroll")                                                           \
    for (int r = 0; r < 2; r++) {                                               \
      int idx = tid + NT_ * r;                                                  \
      int bb = idx >> 5, kk = idx & 31;                                         \
      int kg = kb * 32 + kk;  (void)kg;                                         \
      sm.g.As[bb][kk] = (STAGE_EXPR);                                           \
    }                                                                           \
    __syncthreads();                                                            \
    float4 acc;                                                                 \
    INIT_STMT;                                                                  \
    _Pragma("unroll 8")                                                         \
    for (int k = 0; k < 32; k++) {                                              \
      int kg = kb * 32 + k;                                                     \
      float4 wv = *(const float4*)(WADDR_EXPR);                                 \
      float a = sm.g.As[bb1][k];                                                \
      acc.x += a * wv.x; acc.y += a * wv.y;                                     \
      acc.z += a * wv.z; acc.w += a * wv.w;                                     \
    }                                                                           \
    OUT_STMT;                                                                   \
    __syncthreads();                                                            \
  }

#define ACC_ZERO() do {                                                         \
    acc[0] = make_float4(0.f, 0.f, 0.f, 0.f);                                   \
    acc[1] = make_float4(0.f, 0.f, 0.f, 0.f); } while (0)

__global__ __launch_bounds__(NT_, 1) void mega_kernel(
    const int*   __restrict__ tok,  const float* __restrict__ emb,
    const float* __restrict__ Wp,   const float* __restrict__ bp,
    const float* __restrict__ Wo,   const float* __restrict__ bo,
    const float* __restrict__ g1,   const float* __restrict__ bln1,
    const float* __restrict__ W1,   const float* __restrict__ b1,
    const float* __restrict__ W2,   const float* __restrict__ b2,
    const float* __restrict__ g2,   const float* __restrict__ bln2,
    const float* __restrict__ Wh,   const float* __restrict__ bhw,
    const float* __restrict__ Wf,   const float* __restrict__ bf,
    float* __restrict__ out, int out_size)
{
    extern __shared__ __align__(16) char smem_raw[];
    SM& sm = *reinterpret_cast<SM*>(smem_raw);
    const int blk = blockIdx.x;
    const int tid = threadIdx.x;
    const int lane = tid & 31, wid = tid >> 5;
    const int cg = lane, bg = wid;

    // ========== Stage 1: pos table (ALL blocks) + qw (blk<128) ==========
    // stride NB*NT is a multiple of 512 -> i (and freq) loop-invariant per thread
    {
        int idx0 = blk * NT_ + tid;
        int i = idx0 & 511;
        // 10000^(-2*(i/2)/512) = exp2(-2*log2(10000)/512 * (i/2))
        float freq = exp2f(-0.05190512648261504f * (float)(i >> 1));
        bool isOdd = (i & 1);
        for (int idx = idx0; idx < S_ * D_; idx += NB_ * NT_) {
            int t = idx >> 9;
            float ang = (float)t * freq;
            g_Pos[idx] = isOdd ? cosf(ang) : sinf(ang);
        }
    }
    if (blk < 128) {
        int b = blk >> 2, qt = blk & 3;
        int t0 = tok[b * S_];
        float v = emb[(size_t)t0 * D_ + tid] + (float)(tid & 1);
        sm.q.x0s[tid] = v;
        if (qt == 0) g_x0[b * D_ + tid] = v;
        __syncthreads();

        {   // q0[h,e] with 4 independent accumulator chains
            int h = tid >> 7, e = tid & 127;
            const float* wp = Wp + (size_t)h * D_ * DH_ + e;
            float a0 = 0.f, a1 = 0.f, a2 = 0.f, a3 = 0.f;
#pragma unroll 8
            for (int d = 0; d < D_; d += 4) {
                a0 += sm.q.x0s[d + 0] * wp[(size_t)(d + 0) * DH_];
                a1 += sm.q.x0s[d + 1] * wp[(size_t)(d + 1) * DH_];
                a2 += sm.q.x0s[d + 2] * wp[(size_t)(d + 2) * DH_];
                a3 += sm.q.x0s[d + 3] * wp[(size_t)(d + 3) * DH_];
            }
            sm.q.q0s[tid] = bp[h * DH_ + e] + ((a0 + a1) + (a2 + a3));
        }
        __syncthreads();

        if (qt == 0 && tid < H_) {
            float c = 0.f;
            for (int e = 0; e < 128; e++)
                c += sm.q.q0s[tid * 128 + e] * bp[tid * DH_ + 128 + e];
            g_c[b * H_ + tid] = c;
        }
        {   // w for head qt, d = tid
            const float4* wp4 = (const float4*)(Wp + ((size_t)qt * D_ + tid) * DH_ + 128);
            const float4* q4  = (const float4*)(sm.q.q0s + qt * 128);
            float acc = 0.f;
#pragma unroll
            for (int e4 = 0; e4 < 32; e4++) {
                float4 wv = wp4[e4], qv = q4[e4];
                acc += wv.x * qv.x + wv.y * qv.y + wv.z * qv.z + wv.w * qv.w;
            }
            g_w[b * (H_ * D_) + qt * D_ + tid] = acc;
        }
    }
    grid_bar();

    // ========== Stage C: pipelined gather + alpha + y (128 tiles, 1 sync/iter) ==========
    if (blk < B_ * NCH_) {
        const int b = blk & 31, chunk = blk >> 5;
        const float4* emb4 = (const float4*)emb;
        const float4* pos4 = (const float4*)g_Pos;

        // w cached in registers: wr[h][k] covers f4-group (lane + 32k)
        float4 wr[4][4];
        {
            const float4* gw4 = (const float4*)(g_w + b * (H_ * D_));
#pragma unroll
            for (int h = 0; h < 4; h++)
#pragma unroll
                for (int k = 0; k < 4; k++)
                    wr[h][k] = gw4[h * 128 + lane + 32 * k];
        }
        const float cs0 = g_c[b * H_ + 0];
        const float cs1 = g_c[b * H_ + 1];
        const float cs2 = g_c[b * H_ + 2];
        const float cs3 = g_c[b * H_ + 3];

        const int prow = tid >> 7, pc4 = tid & 127;
        float4 ev[4], pv[4];

        {   // prologue: issue loads for subtile 0
            int r0 = chunk * 256;
#pragma unroll
            for (int r = 0; r < 4; r++) {
                int row = prow + r * 4;
                int tk = tok[b * S_ + r0 + row];
                ev[r] = emb4[(size_t)tk * 128 + pc4];
                pv[r] = pos4[(size_t)(r0 + row) * 128 + pc4];
            }
        }

        float y0 = 0.f, y1 = 0.f, y2 = 0.f, y3 = 0.f;
        float aw0 = 0.f, aw1 = 0.f, aw2 = 0.f, aw3 = 0.f;   // per-warp A accum (lane0)

        for (int sub = 0; sub <= 16; sub++) {
            if (sub < 16) {
                // store prefetched subtile into xs[sub%3]
                float4* xst = (float4*)sm.a.xs[sub % 3];
#pragma unroll
                for (int r = 0; r < 4; r++) {
                    float4 vv;
                    vv.x = ev[r].x + pv[r].x; vv.y = ev[r].y + pv[r].y;
                    vv.z = ev[r].z + pv[r].z; vv.w = ev[r].w + pv[r].w;
                    xst[(prow + r * 4) * 128 + pc4] = vv;
                }
                if (sub < 15) {
                    int r0 = chunk * 256 + (sub + 1) * 16;
#pragma unroll
                    for (int r = 0; r < 4; r++) {
                        int row = prow + r * 4;
                        int tk = tok[b * S_ + r0 + row];
                        ev[r] = emb4[(size_t)tk * 128 + pc4];
                        pv[r] = pos4[(size_t)(r0 + row) * 128 + pc4];
                    }
                }
            }
            __syncthreads();

            if (sub < 16) {
                // alpha(sub): 16 warps, one row each; w from registers
                const float4* xr = (const float4*)&sm.a.xs[sub % 3][wid][0];
                float s0 = 0.f, s1 = 0.f, s2 = 0.f, s3 = 0.f;
#pragma unroll
                for (int k = 0; k < 4; k++) {
                    float4 xv = xr[lane + 32 * k];
                    s0 += xv.x * wr[0][k].x + xv.y * wr[0][k].y
                        + xv.z * wr[0][k].z + xv.w * wr[0][k].w;
                    s1 += xv.x * wr[1][k].x + xv.y * wr[1][k].y
                        + xv.z * wr[1][k].z + xv.w * wr[1][k].w;
                    s2 += xv.x * wr[2][k].x + xv.y * wr[2][k].y
                        + xv.z * wr[2][k].z + xv.w * wr[2][k].w;
                    s3 += xv.x * wr[3][k].x + xv.y * wr[3][k].y
                        + xv.z * wr[3][k].z + xv.w * wr[3][k].w;
                }
#pragma unroll
                for (int off = 16; off > 0; off >>= 1) {
                    s0 += __shfl_xor_sync(0xffffffff, s0, off);
                    s1 += __shfl_xor_sync(0xffffffff, s1, off);
                    s2 += __shfl_xor_sync(0xffffffff, s2, off);
                    s3 += __shfl_xor_sync(0xffffffff, s3, off);
                }
                if (lane == 0) {
                    float a0 = s0 + cs0, a1 = s1 + cs1, a2 = s2 + cs2, a3 = s3 + cs3;
                    sm.a.al[sub & 1][wid][0] = a0;
                    sm.a.al[sub & 1][wid][1] = a1;
                    sm.a.al[sub & 1][wid][2] = a2;
                    sm.a.al[sub & 1][wid][3] = a3;
                    aw0 += a0; aw1 += a1; aw2 += a2; aw3 += a3;
                }
            }
            if (sub >= 1) {
                // y accumulation for subtile sub-1 (al written last iter, xs 2 bufs back)
                int ps = sub - 1;
                const float (*alp)[4] = sm.a.al[ps & 1];
                const float (*xsp)[512] = sm.a.xs[ps % 3];
#pragma unroll
                for (int tt = 0; tt < 16; tt++) {
                    float xv = xsp[tt][tid];
                    float4 a4 = *(const float4*)&alp[tt][0];
                    y0 += a4.x * xv;
                    y1 += a4.y * xv;
                    y2 += a4.z * xv;
                    y3 += a4.w * xv;
                }
            }
        }

        float* yp = g_ypart + ((size_t)(b * NCH_ + chunk)) * (H_ * D_);
        yp[0 * D_ + tid] = y0;
        yp[1 * D_ + tid] = y1;
        yp[2 * D_ + tid] = y2;
        yp[3 * D_ + tid] = y3;

        // A reduction: lane0s deposit per-warp sums, 4 threads reduce across warps
        if (lane == 0) {
            sm.a.al[0][wid][0] = aw0;
            sm.a.al[0][wid][1] = aw1;
            sm.a.al[0][wid][2] = aw2;
            sm.a.al[0][wid][3] = aw3;
        }
        __syncthreads();
        if (tid < H_) {
            float a = 0.f;
#pragma unroll
            for (int w = 0; w < 16; w++) a += sm.a.al[0][w][tid];
            g_Apart[(b * NCH_ + chunk) * H_ + tid] = a;
        }
        __syncthreads();
    }
    grid_bar();

    // ========== F1: heads = y @ Wv + A*bv  (128 tiles of 64 cols) ==========
    GEMM_TILE64(
        /*stage*/ ({
            const int h_ = ct >> 1;
            float s = 0.f;
            _Pragma("unroll")
            for (int c = 0; c < NCH_; c++)
                s += g_ypart[((size_t)(bb * NCH_ + c)) * (H_ * D_) + h_ * D_ + kg];
            s; }),
        /*init*/ do {
            if (kb == 0) {
                const int h_ = ct >> 1;
                float4 bv = *(const float4*)&bp[h_ * DH_ + 256 + (ct & 1) * 64 + cg16 * 4];
                float av = 0.f;
                _Pragma("unroll")
                for (int c = 0; c < NCH_; c++) av += g_Apart[(bb1 * NCH_ + c) * H_ + h_];
                acc.x = av * bv.x; acc.y = av * bv.y;
                acc.z = av * bv.z; acc.w = av * bv.w;
            } else acc = make_float4(0.f, 0.f, 0.f, 0.f);
        } while (0),
        /*W*/ (Wp + ((size_t)(ct >> 1) * D_ + kg) * DH_ + 256 + (ct & 1) * 64 + cg16 * 4),
        /*out*/ do { *(float4*)&g_hp[kb][bb1 * D_ + col] = acc; } while (0));
    grid_bar();

    // ========== F2: x1 = scale*heads @ Wo + bo + x0  (128 tiles) ==========
    GEMM_TILE64(
        /*stage*/ ({
            float s = 0.f;
            _Pragma("unroll")
            for (int p = 0; p < 16; p++) s += g_hp[p][bb * D_ + kg];
            s * 0.03125f; }),
        /*init*/ do {
            if (kb == 0) {
                float4 bv = *(const float4*)&bo[col];
                float4 xv = *(const float4*)&g_x0[bb1 * D_ + col];
                acc.x = bv.x + xv.x; acc.y = bv.y + xv.y;
                acc.z = bv.z + xv.z; acc.w = bv.w + xv.w;
            } else acc = make_float4(0.f, 0.f, 0.f, 0.f);
        } while (0),
        /*W*/ (Wo + (size_t)kg * D_ + col),
        /*out*/ do { *(float4*)&g_x1p[kb][bb1 * D_ + col] = acc; } while (0));
    grid_bar();

    // ========== LN1 ==========
    if (blk < B_) {
        int b = blk;
        float v = 0.f;
#pragma unroll
        for (int p = 0; p < 16; p++) v += g_x1p[p][b * D_ + tid];
        float mu  = redsum(v, sm.r.red) * (1.f / D_);
        float dv  = v - mu;
        float var = redsum(dv * dv, sm.r.red) * (1.f / D_);
        g_x1n[b * D_ + tid] = dv * rsqrtf(var + 1e-3f) * g1[tid] + bln1[tid];
    }
    grid_bar();

    // ========== F3: h1 = x1n @ W1 + b1  (128 tiles) ==========
    GEMM_TILE(16, 8,
        /*stage*/ (g_x1n[bb * D_ + kg]),
        /*init*/ do {
            if (kb == 0) {
                float4 bv = *(const float4*)&b1[col];
                acc[0] = bv; acc[1] = bv;
            } else ACC_ZERO();
        } while (0),
        /*W*/ (W1 + (size_t)kg * FFN_ + col),
        /*out*/ do {
            _Pragma("unroll")
            for (int j = 0; j < 2; j++)
                *(float4*)&g_h1p[kb][(bg * 2 + j) * FFN_ + col] = acc[j];
        } while (0));
    grid_bar();

    // ========== F4: x2 = relu(h1) @ W2 + b2 + x1n  (128 tiles) ==========
    GEMM_TILE(4, 32,
        /*stage*/ ({
            float s = 0.f;
            _Pragma("unroll")
            for (int p = 0; p < 8; p++) s += g_h1p[p][bb * FFN_ + kg];
            fmaxf(s, 0.f); }),
        /*init*/ do {
            if (kb == 0) {
                float4 bv = *(const float4*)&b2[col];
                _Pragma("unroll")
                for (int j = 0; j < 2; j++) {
                    float4 xv = *(const float4*)&g_x1n[(bg * 2 + j) * D_ + col];
                    acc[j].x = bv.x + xv.x; acc[j].y = bv.y + xv.y;
                    acc[j].z = bv.z + xv.z; acc[j].w = bv.w + xv.w;
                }
            } else ACC_ZERO();
        } while (0),
        /*W*/ (W2 + (size_t)kg * D_ + col),
        /*out*/ do {
            _Pragma("unroll")
            for (int j = 0; j < 2; j++)
                *(float4*)&g_x2p[kb][(bg * 2 + j) * D_ + col] = acc[j];
        } while (0));
    grid_bar();

    // ========== LN2 ==========
    if (blk < B_) {
        int b = blk;
        float v = 0.f;
#pragma unroll
        for (int p = 0; p < 32; p++) v += g_x2p[p][b * D_ + tid];
        float mu  = redsum(v, sm.r.red) * (1.f / D_);
        float dv  = v - mu;
        float var = redsum(dv * dv, sm.r.red) * (1.f / D_);
        g_x2[b * D_ + tid] = dv * rsqrtf(var + 1e-3f) * g2[tid] + bln2[tid];
    }
    grid_bar();

    // ========== F5: hid = x2 @ Wh + bh  (128 tiles) ==========
    GEMM_TILE64(
        /*stage*/ (g_x2[bb * D_ + kg]),
        /*init*/ do {
            if (kb == 0) {
                acc = *(const float4*)&bhw[col];
            } else acc = make_float4(0.f, 0.f, 0.f, 0.f);
        } while (0),
        /*W*/ (Wh + (size_t)kg * D_ + col),
        /*out*/ do { *(float4*)&g_hidp[kb][bb1 * D_ + col] = acc; } while (0));
    grid_bar();

    // ========== logits ==========
    if (blk < B_) {
        int b = blk;
        float v = 0.f;
#pragma unroll
        for (int p = 0; p < 16; p++) v += g_hidp[p][b * D_ + tid];
        float hid = fmaxf(v, 0.f);
        float s = redsum(hid * Wf[tid], sm.r.red);
        if (tid == 0) {
            float logit = s + bf[0];
            if (b < out_size)      out[b]      = logit;
            if (B_ + b < out_size) out[B_ + b] = 1.f / (1.f + expf(-logit));
        }
    }
}

// ---------------------------------------------------------------------------
extern "C" void kernel_launch(void* const* d_in, const int* in_sizes, int n_in,
                              void* d_out, int out_size) {
    const int*   inputs = (const int*)  d_in[0];
    const float* emb    = (const float*)d_in[1];
    const float* Wp     = (const float*)d_in[2];
    const float* bp     = (const float*)d_in[3];
    const float* Wo     = (const float*)d_in[4];
    const float* bo     = (const float*)d_in[5];
    const float* ln1g   = (const float*)d_in[6];
    const float* ln1b   = (const float*)d_in[7];
    const float* W1     = (const float*)d_in[8];
    const float* b1     = (const float*)d_in[9];
    const float* W2     = (const float*)d_in[10];
    const float* b2     = (const float*)d_in[11];
    const float* ln2g   = (const float*)d_in[12];
    const float* ln2b   = (const float*)d_in[13];
    const float* Wh     = (const float*)d_in[14];
    const float* bhp    = (const float*)d_in[15];
    const float* Wf     = (const float*)d_in[16];
    const float* bf     = (const float*)d_in[17];
    float* out = (float*)d_out;

    static_assert(sizeof(SM) < 200 * 1024, "smem budget");
    cudaFuncSetAttribute(mega_kernel,
                         cudaFuncAttributeMaxDynamicSharedMemorySize,
                         (int)sizeof(SM));
    mega_kernel<<<NB_, NT_, sizeof(SM)>>>(inputs, emb, Wp, bp, Wo, bo,
                                          ln1g, ln1b, W1, b1, W2, b2,
                                          ln2g, ln2b, Wh, bhp, Wf, bf,
                                          out, out_size);
}

// round 16
// speedup vs baseline: 1.4307x; 1.0308x over previous
#include <cuda_runtime.h>
#include <math.h>

namespace {
constexpr int B_   = 32;
constexpr int S_   = 1024;
constexpr int D_   = 512;
constexpr int H_   = 4;
constexpr int DH_  = 384;
constexpr int FFN_ = 2048;
constexpr int NCH_ = 4;     // 256-row chunks for alpha/y -> 128 tiles (1 wave)
constexpr int NB_  = 148;   // one block per SM — all resident
constexpr int NT_  = 512;
}

// ---------------- static scratch ----------------
__device__ float g_Pos[S_ * D_];                  // 2 MB
__device__ float g_x0[B_ * D_];
__device__ float g_w[B_ * H_ * D_];
__device__ float g_c[B_ * H_];
__device__ float g_ypart[B_ * NCH_ * H_ * D_];    // 1 MB
__device__ float g_Apart[B_ * NCH_ * H_];
__device__ float g_hp[16][B_ * D_];               // F1 partials
__device__ float g_x1p[16][B_ * D_];              // F2 partials
__device__ float g_x1n[B_ * D_];                  // post-LN1
__device__ float g_h1p[8][B_ * FFN_];             // F3 partials
__device__ float g_x2p[32][B_ * D_];              // F4 partials
__device__ float g_x2[B_ * D_];                   // post-LN2
__device__ float g_hidp[16][B_ * D_];             // F5 partials

// ---------------- grid barrier (flat — measured cheap) ----------------
__device__ unsigned g_cnt = 0;
__device__ volatile unsigned g_gen = 0;

__device__ __forceinline__ void grid_bar() {
    __syncthreads();
    if (threadIdx.x == 0) {
        unsigned gen = g_gen;               // read BEFORE arriving
        __threadfence();                    // release
        if (atomicAdd(&g_cnt, 1u) == NB_ - 1u) {
            g_cnt = 0;
            __threadfence();
            g_gen = gen + 1u;
        } else {
            while (g_gen == gen) __nanosleep(64);
        }
        __threadfence();                    // acquire
    }
    __syncthreads();
}

// ---------------- shared memory union (dynamic) ----------------
struct SA { float xs[3][16][512]; float al[2][16][4]; };   // 96.5 KB
struct SG { float As[32][64]; };
struct SQ { float x0s[512]; float q0s[512]; float q0p[2048]; };
struct SR { float red[32]; };
union  SM { SA a; SG g; SQ q; SR r; };

// block reduction over 512 threads: warp shuffle + cross-warp shuffle
__device__ __forceinline__ float redsum(float v, float* red) {
    int tid = threadIdx.x;
    int lane = tid & 31, w = tid >> 5;
#pragma unroll
    for (int off = 16; off > 0; off >>= 1)
        v += __shfl_xor_sync(0xffffffff, v, off);
    if (lane == 0) red[w] = v;
    __syncthreads();
    float r = red[lane & 15];
    if (w == 0) {
#pragma unroll
        for (int off = 8; off > 0; off >>= 1)
            r += __shfl_xor_sync(0xffffffff, r, off);
        if (lane == 0) red[0] = r;
    }
    __syncthreads();
    r = red[0];
    __syncthreads();   // protect red for next call
    return r;
}

// 128-col tiles: C[32, NCT*128] += A[32, NKT*64] @ W (F3/F4)
#define GEMM_TILE(NCT, NKT, STAGE_EXPR, INIT_STMT, WADDR_EXPR, OUT_STMT)        \
  if (blk < (NCT) * (NKT)) {                                                    \
    const int ct = blk / (NKT), kb = blk % (NKT);                               \
    const int col = ct * 128 + cg * 4;  (void)col;                              \
    _Pragma("unroll")                                                           \
    for (int r = 0; r < 4; r++) {                                               \
      int idx = tid + NT_ * r;                                                  \
      int bb = idx >> 6, kk = idx & 63;                                         \
      int kg = kb * 64 + kk;  (void)kg;                                         \
      sm.g.As[bb][kk] = (STAGE_EXPR);                                           \
    }                                                                           \
    __syncthreads();                                                            \
    float4 acc[2];                                                              \
    INIT_STMT;                                                                  \
    _Pragma("unroll 8")                                                         \
    for (int k = 0; k < 64; k++) {                                              \
      int kg = kb * 64 + k;                                                     \
      float4 wv = *(const float4*)(WADDR_EXPR);                                 \
      _Pragma("unroll")                                                         \
      for (int j = 0; j < 2; j++) {                                             \
        float a = sm.g.As[bg * 2 + j][k];                                       \
        acc[j].x += a * wv.x; acc[j].y += a * wv.y;                             \
        acc[j].z += a * wv.z; acc[j].w += a * wv.w;                             \
      }                                                                         \
    }                                                                           \
    OUT_STMT;                                                                   \
    __syncthreads();                                                            \
  }

// 64-col tiles, 128 blocks: 8 col-tiles x 16 K-splits (slice 32), 1 batch/thread.
#define GEMM_TILE64(STAGE_EXPR, INIT_STMT, WADDR_EXPR, OUT_STMT)                \
  if (blk < 128) {                                                              \
    const int ct = blk >> 4, kb = blk & 15;                                     \
    const int cg16 = tid & 15, bb1 = tid >> 4;                                  \
    const int col = ct * 64 + cg16 * 4;  (void)col; (void)bb1;                  \
    _Pragma("unroll")                                                           \
    for (int r = 0; r < 2; r++) {                                               \
      int idx = tid + NT_ * r;                                                  \
      int bb = idx >> 5, kk = idx & 31;                                         \
      int kg = kb * 32 + kk;  (void)kg;                                         \
      sm.g.As[bb][kk] = (STAGE_EXPR);                                           \
    }                                                                           \
    __syncthreads();                                                            \
    float4 acc;                                                                 \
    INIT_STMT;                                                                  \
    _Pragma("unroll 16")                                                        \
    for (int k = 0; k < 32; k++) {                                              \
      int kg = kb * 32 + k;                                                     \
      float4 wv = *(const float4*)(WADDR_EXPR);                                 \
      float a = sm.g.As[bb1][k];                                                \
      acc.x += a * wv.x; acc.y += a * wv.y;                                     \
      acc.z += a * wv.z; acc.w += a * wv.w;                                     \
    }                                                                           \
    OUT_STMT;                                                                   \
    __syncthreads();                                                            \
  }

#define ACC_ZERO() do {                                                         \
    acc[0] = make_float4(0.f, 0.f, 0.f, 0.f);                                   \
    acc[1] = make_float4(0.f, 0.f, 0.f, 0.f); } while (0)

__global__ __launch_bounds__(NT_, 1) void mega_kernel(
    const int*   __restrict__ tok,  const float* __restrict__ emb,
    const float* __restrict__ Wp,   const float* __restrict__ bp,
    const float* __restrict__ Wo,   const float* __restrict__ bo,
    const float* __restrict__ g1,   const float* __restrict__ bln1,
    const float* __restrict__ W1,   const float* __restrict__ b1,
    const float* __restrict__ W2,   const float* __restrict__ b2,
    const float* __restrict__ g2,   const float* __restrict__ bln2,
    const float* __restrict__ Wh,   const float* __restrict__ bhw,
    const float* __restrict__ Wf,   const float* __restrict__ bf,
    float* __restrict__ out, int out_size)
{
    extern __shared__ __align__(16) char smem_raw[];
    SM& sm = *reinterpret_cast<SM*>(smem_raw);
    const int blk = blockIdx.x;
    const int tid = threadIdx.x;
    const int lane = tid & 31, wid = tid >> 5;
    const int cg = lane, bg = wid;

    // ========== Stage 1: pos table (ALL blocks) + qw (blk<128) ==========
    // stride NB*NT is a multiple of 512 -> i (and freq) loop-invariant per thread
    {
        int idx0 = blk * NT_ + tid;
        int i = idx0 & 511;
        // 10000^(-2*(i/2)/512) = exp2(-2*log2(10000)/512 * (i/2))
        float freq = exp2f(-0.05190512648261504f * (float)(i >> 1));
        bool isOdd = (i & 1);
        for (int idx = idx0; idx < S_ * D_; idx += NB_ * NT_) {
            int t = idx >> 9;
            float ang = (float)t * freq;
            g_Pos[idx] = isOdd ? cosf(ang) : sinf(ang);
        }
    }
    if (blk < 128) {
        int b = blk >> 2, qt = blk & 3;
        int t0 = tok[b * S_];
        float v = emb[(size_t)t0 * D_ + tid] + (float)(tid & 1);
        sm.q.x0s[tid] = v;
        if (qt == 0) g_x0[b * D_ + tid] = v;
        __syncthreads();

        {   // q0 partials: thread = (d-quarter, h*32+e4). LDG.128 over e (coalesced).
            int quarter = tid >> 7;              // d-split 0..3
            int g = tid & 127;                   // = h*32 + e4
            int h = g >> 5;
            int e4 = g & 31;
            const float4* wrow =
                (const float4*)(Wp + ((size_t)h * D_ + quarter * 128) * DH_) + e4;
            const float* xq = sm.q.x0s + quarter * 128;
            float4 acc = make_float4(0.f, 0.f, 0.f, 0.f);
#pragma unroll 8
            for (int d = 0; d < 128; d++) {
                float4 wv = wrow[(size_t)d * (DH_ / 4)];
                float x = xq[d];
                acc.x += x * wv.x; acc.y += x * wv.y;
                acc.z += x * wv.z; acc.w += x * wv.w;
            }
            ((float4*)sm.q.q0p)[quarter * 128 + g] = acc;
        }
        __syncthreads();

        if (tid < 128) {   // reduce quarters + bias -> q0s (float4 group = tid)
            const float4* p = (const float4*)sm.q.q0p;
            float4 a = p[tid], bq = p[128 + tid], cq = p[256 + tid], dq = p[384 + tid];
            int h = tid >> 5, e4 = tid & 31;
            float4 bias = *(const float4*)&bp[h * DH_ + e4 * 4];
            float4 q;
            q.x = bias.x + ((a.x + bq.x) + (cq.x + dq.x));
            q.y = bias.y + ((a.y + bq.y) + (cq.y + dq.y));
            q.z = bias.z + ((a.z + bq.z) + (cq.z + dq.z));
            q.w = bias.w + ((a.w + bq.w) + (cq.w + dq.w));
            ((float4*)sm.q.q0s)[tid] = q;
        }
        __syncthreads();

        if (qt == 0 && wid < 4) {   // c_h: warp h, warp-parallel dot
            float val = 0.f;
#pragma unroll
            for (int k = 0; k < 4; k++) {
                int e = lane + 32 * k;
                val += sm.q.q0s[wid * 128 + e] * bp[wid * DH_ + 128 + e];
            }
#pragma unroll
            for (int off = 16; off > 0; off >>= 1)
                val += __shfl_xor_sync(0xffffffff, val, off);
            if (lane == 0) g_c[b * H_ + wid] = val;
        }
        {   // w for head qt, d = tid
            const float4* wp4 = (const float4*)(Wp + ((size_t)qt * D_ + tid) * DH_ + 128);
            const float4* q4  = (const float4*)(sm.q.q0s + qt * 128);
            float acc = 0.f;
#pragma unroll
            for (int e4 = 0; e4 < 32; e4++) {
                float4 wv = wp4[e4], qv = q4[e4];
                acc += wv.x * qv.x + wv.y * qv.y + wv.z * qv.z + wv.w * qv.w;
            }
            g_w[b * (H_ * D_) + qt * D_ + tid] = acc;
        }
    }
    grid_bar();

    // ========== Stage C: pipelined gather + alpha + y (128 tiles, 1 sync/iter) ==========
    if (blk < B_ * NCH_) {
        const int b = blk & 31, chunk = blk >> 5;
        const float4* emb4 = (const float4*)emb;
        const float4* pos4 = (const float4*)g_Pos;

        // w cached in registers: wr[h][k] covers f4-group (lane + 32k)
        float4 wr[4][4];
        {
            const float4* gw4 = (const float4*)(g_w + b * (H_ * D_));
#pragma unroll
            for (int h = 0; h < 4; h++)
#pragma unroll
                for (int k = 0; k < 4; k++)
                    wr[h][k] = gw4[h * 128 + lane + 32 * k];
        }
        const float cs0 = g_c[b * H_ + 0];
        const float cs1 = g_c[b * H_ + 1];
        const float cs2 = g_c[b * H_ + 2];
        const float cs3 = g_c[b * H_ + 3];

        const int prow = tid >> 7, pc4 = tid & 127;
        float4 ev[4], pv[4];

        {   // prologue: issue loads for subtile 0
            int r0 = chunk * 256;
#pragma unroll
            for (int r = 0; r < 4; r++) {
                int row = prow + r * 4;
                int tk = tok[b * S_ + r0 + row];
                ev[r] = emb4[(size_t)tk * 128 + pc4];
                pv[r] = pos4[(size_t)(r0 + row) * 128 + pc4];
            }
        }

        float y0 = 0.f, y1 = 0.f, y2 = 0.f, y3 = 0.f;
        float aw0 = 0.f, aw1 = 0.f, aw2 = 0.f, aw3 = 0.f;   // per-warp A accum (lane0)

        for (int sub = 0; sub <= 16; sub++) {
            if (sub < 16) {
                // store prefetched subtile into xs[sub%3]
                float4* xst = (float4*)sm.a.xs[sub % 3];
#pragma unroll
                for (int r = 0; r < 4; r++) {
                    float4 vv;
                    vv.x = ev[r].x + pv[r].x; vv.y = ev[r].y + pv[r].y;
                    vv.z = ev[r].z + pv[r].z; vv.w = ev[r].w + pv[r].w;
                    xst[(prow + r * 4) * 128 + pc4] = vv;
                }
                if (sub < 15) {
                    int r0 = chunk * 256 + (sub + 1) * 16;
#pragma unroll
                    for (int r = 0; r < 4; r++) {
                        int row = prow + r * 4;
                        int tk = tok[b * S_ + r0 + row];
                        ev[r] = emb4[(size_t)tk * 128 + pc4];
                        pv[r] = pos4[(size_t)(r0 + row) * 128 + pc4];
                    }
                }
            }
            __syncthreads();

            if (sub < 16) {
                // alpha(sub): 16 warps, one row each; w from registers
                const float4* xr = (const float4*)&sm.a.xs[sub % 3][wid][0];
                float s0 = 0.f, s1 = 0.f, s2 = 0.f, s3 = 0.f;
#pragma unroll
                for (int k = 0; k < 4; k++) {
                    float4 xv = xr[lane + 32 * k];
                    s0 += xv.x * wr[0][k].x + xv.y * wr[0][k].y
                        + xv.z * wr[0][k].z + xv.w * wr[0][k].w;
                    s1 += xv.x * wr[1][k].x + xv.y * wr[1][k].y
                        + xv.z * wr[1][k].z + xv.w * wr[1][k].w;
                    s2 += xv.x * wr[2][k].x + xv.y * wr[2][k].y
                        + xv.z * wr[2][k].z + xv.w * wr[2][k].w;
                    s3 += xv.x * wr[3][k].x + xv.y * wr[3][k].y
                        + xv.z * wr[3][k].z + xv.w * wr[3][k].w;
                }
#pragma unroll
                for (int off = 16; off > 0; off >>= 1) {
                    s0 += __shfl_xor_sync(0xffffffff, s0, off);
                    s1 += __shfl_xor_sync(0xffffffff, s1, off);
                    s2 += __shfl_xor_sync(0xffffffff, s2, off);
                    s3 += __shfl_xor_sync(0xffffffff, s3, off);
                }
                if (lane == 0) {
                    float a0 = s0 + cs0, a1 = s1 + cs1, a2 = s2 + cs2, a3 = s3 + cs3;
                    sm.a.al[sub & 1][wid][0] = a0;
                    sm.a.al[sub & 1][wid][1] = a1;
                    sm.a.al[sub & 1][wid][2] = a2;
                    sm.a.al[sub & 1][wid][3] = a3;
                    aw0 += a0; aw1 += a1; aw2 += a2; aw3 += a3;
                }
            }
            if (sub >= 1) {
                // y accumulation for subtile sub-1 (al written last iter, xs 2 bufs back)
                int ps = sub - 1;
                const float (*alp)[4] = sm.a.al[ps & 1];
                const float (*xsp)[512] = sm.a.xs[ps % 3];
#pragma unroll
                for (int tt = 0; tt < 16; tt++) {
                    float xv = xsp[tt][tid];
                    float4 a4 = *(const float4*)&alp[tt][0];
                    y0 += a4.x * xv;
                    y1 += a4.y * xv;
                    y2 += a4.z * xv;
                    y3 += a4.w * xv;
                }
            }
        }

        float* yp = g_ypart + ((size_t)(b * NCH_ + chunk)) * (H_ * D_);
        yp[0 * D_ + tid] = y0;
        yp[1 * D_ + tid] = y1;
        yp[2 * D_ + tid] = y2;
        yp[3 * D_ + tid] = y3;

        // A reduction: lane0s deposit per-warp sums, 4 threads reduce across warps
        if (lane == 0) {
            sm.a.al[0][wid][0] = aw0;
            sm.a.al[0][wid][1] = aw1;
            sm.a.al[0][wid][2] = aw2;
            sm.a.al[0][wid][3] = aw3;
        }
        __syncthreads();
        if (tid < H_) {
            float a = 0.f;
#pragma unroll
            for (int w = 0; w < 16; w++) a += sm.a.al[0][w][tid];
            g_Apart[(b * NCH_ + chunk) * H_ + tid] = a;
        }
        __syncthreads();
    }
    grid_bar();

    // ========== F1: heads = y @ Wv + A*bv  (128 tiles of 64 cols) ==========
    GEMM_TILE64(
        /*stage*/ ({
            const int h_ = ct >> 1;
            float s = 0.f;
            _Pragma("unroll")
            for (int c = 0; c < NCH_; c++)
                s += g_ypart[((size_t)(bb * NCH_ + c)) * (H_ * D_) + h_ * D_ + kg];
            s; }),
        /*init*/ do {
            if (kb == 0) {
                const int h_ = ct >> 1;
                float4 bv = *(const float4*)&bp[h_ * DH_ + 256 + (ct & 1) * 64 + cg16 * 4];
                float av = 0.f;
                _Pragma("unroll")
                for (int c = 0; c < NCH_; c++) av += g_Apart[(bb1 * NCH_ + c) * H_ + h_];
                acc.x = av * bv.x; acc.y = av * bv.y;
                acc.z = av * bv.z; acc.w = av * bv.w;
            } else acc = make_float4(0.f, 0.f, 0.f, 0.f);
        } while (0),
        /*W*/ (Wp + ((size_t)(ct >> 1) * D_ + kg) * DH_ + 256 + (ct & 1) * 64 + cg16 * 4),
        /*out*/ do { *(float4*)&g_hp[kb][bb1 * D_ + col] = acc; } while (0));
    grid_bar();

    // ========== F2: x1 = scale*heads @ Wo + bo + x0  (128 tiles) ==========
    GEMM_TILE64(
        /*stage*/ ({
            float s = 0.f;
            _Pragma("unroll")
            for (int p = 0; p < 16; p++) s += g_hp[p][bb * D_ + kg];
            s * 0.03125f; }),
        /*init*/ do {
            if (kb == 0) {
                float4 bv = *(const float4*)&bo[col];
                float4 xv = *(const float4*)&g_x0[bb1 * D_ + col];
                acc.x = bv.x + xv.x; acc.y = bv.y + xv.y;
                acc.z = bv.z + xv.z; acc.w = bv.w + xv.w;
            } else acc = make_float4(0.f, 0.f, 0.f, 0.f);
        } while (0),
        /*W*/ (Wo + (size_t)kg * D_ + col),
        /*out*/ do { *(float4*)&g_x1p[kb][bb1 * D_ + col] = acc; } while (0));
    grid_bar();

    // ========== LN1 ==========
    if (blk < B_) {
        int b = blk;
        float v = 0.f;
#pragma unroll
        for (int p = 0; p < 16; p++) v += g_x1p[p][b * D_ + tid];
        float mu  = redsum(v, sm.r.red) * (1.f / D_);
        float dv  = v - mu;
        float var = redsum(dv * dv, sm.r.red) * (1.f / D_);
        g_x1n[b * D_ + tid] = dv * rsqrtf(var + 1e-3f) * g1[tid] + bln1[tid];
    }
    grid_bar();

    // ========== F3: h1 = x1n @ W1 + b1  (128 tiles) ==========
    GEMM_TILE(16, 8,
        /*stage*/ (g_x1n[bb * D_ + kg]),
        /*init*/ do {
            if (kb == 0) {
                float4 bv = *(const float4*)&b1[col];
                acc[0] = bv; acc[1] = bv;
            } else ACC_ZERO();
        } while (0),
        /*W*/ (W1 + (size_t)kg * FFN_ + col),
        /*out*/ do {
            _Pragma("unroll")
            for (int j = 0; j < 2; j++)
                *(float4*)&g_h1p[kb][(bg * 2 + j) * FFN_ + col] = acc[j];
        } while (0));
    grid_bar();

    // ========== F4: x2 = relu(h1) @ W2 + b2 + x1n  (128 tiles) ==========
    GEMM_TILE(4, 32,
        /*stage*/ ({
            float s = 0.f;
            _Pragma("unroll")
            for (int p = 0; p < 8; p++) s += g_h1p[p][bb * FFN_ + kg];
            fmaxf(s, 0.f); }),
        /*init*/ do {
            if (kb == 0) {
                float4 bv = *(const float4*)&b2[col];
                _Pragma("unroll")
                for (int j = 0; j < 2; j++) {
                    float4 xv = *(const float4*)&g_x1n[(bg * 2 + j) * D_ + col];
                    acc[j].x = bv.x + xv.x; acc[j].y = bv.y + xv.y;
                    acc[j].z = bv.z + xv.z; acc[j].w = bv.w + xv.w;
                }
            } else ACC_ZERO();
        } while (0),
        /*W*/ (W2 + (size_t)kg * D_ + col),
        /*out*/ do {
            _Pragma("unroll")
            for (int j = 0; j < 2; j++)
                *(float4*)&g_x2p[kb][(bg * 2 + j) * D_ + col] = acc[j];
        } while (0));
    grid_bar();

    // ========== LN2 ==========
    if (blk < B_) {
        int b = blk;
        float v = 0.f;
#pragma unroll
        for (int p = 0; p < 32; p++) v += g_x2p[p][b * D_ + tid];
        float mu  = redsum(v, sm.r.red) * (1.f / D_);
        float dv  = v - mu;
        float var = redsum(dv * dv, sm.r.red) * (1.f / D_);
        g_x2[b * D_ + tid] = dv * rsqrtf(var + 1e-3f) * g2[tid] + bln2[tid];
    }
    grid_bar();

    // ========== F5: hid = x2 @ Wh + bh  (128 tiles) ==========
    GEMM_TILE64(
        /*stage*/ (g_x2[bb * D_ + kg]),
        /*init*/ do {
            if (kb == 0) {
                acc = *(const float4*)&bhw[col];
            } else acc = make_float4(0.f, 0.f, 0.f, 0.f);
        } while (0),
        /*W*/ (Wh + (size_t)kg * D_ + col),
        /*out*/ do { *(float4*)&g_hidp[kb][bb1 * D_ + col] = acc; } while (0));
    grid_bar();

    // ========== logits ==========
    if (blk < B_) {
        int b = blk;
        float v = 0.f;
#pragma unroll
        for (int p = 0; p < 16; p++) v += g_hidp[p][b * D_ + tid];
        float hid = fmaxf(v, 0.f);
        float s = redsum(hid * Wf[tid], sm.r.red);
        if (tid == 0) {
            float logit = s + bf[0];
            if (b < out_size)      out[b]      = logit;
            if (B_ + b < out_size) out[B_ + b] = 1.f / (1.f + expf(-logit));
        }
    }
}

// ---------------------------------------------------------------------------
extern "C" void kernel_launch(void* const* d_in, const int* in_sizes, int n_in,
                              void* d_out, int out_size) {
    const int*   inputs = (const int*)  d_in[0];
    const float* emb    = (const float*)d_in[1];
    const float* Wp     = (const float*)d_in[2];
    const float* bp     = (const float*)d_in[3];
    const float* Wo     = (const float*)d_in[4];
    const float* bo     = (const float*)d_in[5];
    const float* ln1g   = (const float*)d_in[6];
    const float* ln1b   = (const float*)d_in[7];
    const float* W1     = (const float*)d_in[8];
    const float* b1     = (const float*)d_in[9];
    const float* W2     = (const float*)d_in[10];
    const float* b2     = (const float*)d_in[11];
    const float* ln2g   = (const float*)d_in[12];
    const float* ln2b   = (const float*)d_in[13];
    const float* Wh     = (const float*)d_in[14];
    const float* bhp    = (const float*)d_in[15];
    const float* Wf     = (const float*)d_in[16];
    const float* bf     = (const float*)d_in[17];
    float* out = (float*)d_out;

    static_assert(sizeof(SM) < 200 * 1024, "smem budget");
    cudaFuncSetAttribute(mega_kernel,
                         cudaFuncAttributeMaxDynamicSharedMemorySize,
                         (int)sizeof(SM));
    mega_kernel<<<NB_, NT_, sizeof(SM)>>>(inputs, emb, Wp, bp, Wo, bo,
                                          ln1g, ln1b, W1, b1, W2, b2,
                                          ln2g, ln2b, Wh, bhp, Wf, bf,
                                          out, out_size);
}

// round 17
// speedup vs baseline: 1.4408x; 1.0071x over previous
#include <cuda_runtime.h>
#include <math.h>

namespace {
constexpr int B_   = 32;
constexpr int S_   = 1024;
constexpr int D_   = 512;
constexpr int H_   = 4;
constexpr int DH_  = 384;
constexpr int FFN_ = 2048;
constexpr int NCH_ = 4;     // 256-row chunks for alpha/y -> 128 tiles (1 wave)
constexpr int NB_  = 148;   // one block per SM — all resident
constexpr int NT_  = 512;
}

// ---------------- static scratch ----------------
__device__ float g_Pos[S_ * D_];                  // 2 MB
__device__ float g_x0[B_ * D_];
__device__ float g_w[B_ * H_ * D_];
__device__ float g_c[B_ * H_];
__device__ float g_ypart[B_ * NCH_ * H_ * D_];    // 1 MB
__device__ float g_Apart[B_ * NCH_ * H_];
__device__ float g_hp[16][B_ * D_];               // F1 partials
__device__ float g_x1p[16][B_ * D_];              // F2 partials
__device__ float g_x1n[B_ * D_];                  // post-LN1
__device__ float g_h1p[8][B_ * FFN_];             // F3 partials
__device__ float g_x2p[32][B_ * D_];              // F4 partials
__device__ float g_x2[B_ * D_];                   // post-LN2
__device__ float g_hidp[16][B_ * D_];             // F5 partials

// ---------------- grid barrier (flat — measured cheap) ----------------
__device__ unsigned g_cnt = 0;
__device__ volatile unsigned g_gen = 0;

__device__ __forceinline__ void grid_bar() {
    __syncthreads();
    if (threadIdx.x == 0) {
        unsigned gen = g_gen;               // read BEFORE arriving
        __threadfence();                    // release
        if (atomicAdd(&g_cnt, 1u) == NB_ - 1u) {
            g_cnt = 0;
            __threadfence();
            g_gen = gen + 1u;
        } else {
            while (g_gen == gen) __nanosleep(64);
        }
        __threadfence();                    // acquire
    }
    __syncthreads();
}

// ---------------- shared memory union (dynamic) ----------------
struct SA { float xs[3][16][512]; float al[2][16][4]; int toks[256]; };
struct SG { float As[32][64]; };
struct SQ { float x0s[512]; float q0s[512]; float q0p[2048]; };
struct SR { float red[32]; };
union  SM { SA a; SG g; SQ q; SR r; };

// block reduction over 512 threads: warp shuffle + cross-warp shuffle
__device__ __forceinline__ float redsum(float v, float* red) {
    int tid = threadIdx.x;
    int lane = tid & 31, w = tid >> 5;
#pragma unroll
    for (int off = 16; off > 0; off >>= 1)
        v += __shfl_xor_sync(0xffffffff, v, off);
    if (lane == 0) red[w] = v;
    __syncthreads();
    float r = red[lane & 15];
    if (w == 0) {
#pragma unroll
        for (int off = 8; off > 0; off >>= 1)
            r += __shfl_xor_sync(0xffffffff, r, off);
        if (lane == 0) red[0] = r;
    }
    __syncthreads();
    r = red[0];
    __syncthreads();   // protect red for next call
    return r;
}

// 128-col tiles: C[32, NCT*128] += A[32, NKT*64] @ W (F3/F4)
#define GEMM_TILE(NCT, NKT, STAGE_EXPR, INIT_STMT, WADDR_EXPR, OUT_STMT)        \
  if (blk < (NCT) * (NKT)) {                                                    \
    const int ct = blk / (NKT), kb = blk % (NKT);                               \
    const int col = ct * 128 + cg * 4;  (void)col;                              \
    _Pragma("unroll")                                                           \
    for (int r = 0; r < 4; r++) {                                               \
      int idx = tid + NT_ * r;                                                  \
      int bb = idx >> 6, kk = idx & 63;                                         \
      int kg = kb * 64 + kk;  (void)kg;                                         \
      sm.g.As[bb][kk] = (STAGE_EXPR);                                           \
    }                                                                           \
    __syncthreads();                                                            \
    float4 acc[2];                                                              \
    INIT_STMT;                                                                  \
    _Pragma("unroll 16")                                                        \
    for (int k = 0; k < 64; k++) {                                              \
      int kg = kb * 64 + k;                                                     \
      float4 wv = *(const float4*)(WADDR_EXPR);                                 \
      _Pragma("unroll")                                                         \
      for (int j = 0; j < 2; j++) {                                             \
        float a = sm.g.As[bg * 2 + j][k];                                       \
        acc[j].x += a * wv.x; acc[j].y += a * wv.y;                             \
        acc[j].z += a * wv.z; acc[j].w += a * wv.w;                             \
      }                                                                         \
    }                                                                           \
    OUT_STMT;                                                                   \
    __syncthreads();                                                            \
  }

// 64-col tiles, 128 blocks: 8 col-tiles x 16 K-splits (slice 32), 1 batch/thread.
#define GEMM_TILE64(STAGE_EXPR, INIT_STMT, WADDR_EXPR, OUT_STMT)                \
  if (blk < 128) {                                                              \
    const int ct = blk >> 4, kb = blk & 15;                                     \
    const int cg16 = tid & 15, bb1 = tid >> 4;                                  \
    const int col = ct * 64 + cg16 * 4;  (void)col; (void)bb1;                  \
    _Pragma("unroll")                                                           \
    for (int r = 0; r < 2; r++) {                                               \
      int idx = tid + NT_ * r;                                                  \
      int bb = idx >> 5, kk = idx & 31;                                         \
      int kg = kb * 32 + kk;  (void)kg;                                         \
      sm.g.As[bb][kk] = (STAGE_EXPR);                                           \
    }                                                                           \
    __syncthreads();                                                            \
    float4 acc;                                                                 \
    INIT_STMT;                                                                  \
    _Pragma("unroll 16")                                                        \
    for (int k = 0; k < 32; k++) {                                              \
      int kg = kb * 32 + k;                                                     \
      float4 wv = *(const float4*)(WADDR_EXPR);                                 \
      float a = sm.g.As[bb1][k];                                                \
      acc.x += a * wv.x; acc.y += a * wv.y;                                     \
      acc.z += a * wv.z; acc.w += a * wv.w;                                     \
    }                                                                           \
    OUT_STMT;                                                                   \
    __syncthreads();                                                            \
  }

#define ACC_ZERO() do {                                                         \
    acc[0] = make_float4(0.f, 0.f, 0.f, 0.f);                                   \
    acc[1] = make_float4(0.f, 0.f, 0.f, 0.f); } while (0)

__global__ __launch_bounds__(NT_, 1) void mega_kernel(
    const int*   __restrict__ tok,  const float* __restrict__ emb,
    const float* __restrict__ Wp,   const float* __restrict__ bp,
    const float* __restrict__ Wo,   const float* __restrict__ bo,
    const float* __restrict__ g1,   const float* __restrict__ bln1,
    const float* __restrict__ W1,   const float* __restrict__ b1,
    const float* __restrict__ W2,   const float* __restrict__ b2,
    const float* __restrict__ g2,   const float* __restrict__ bln2,
    const float* __restrict__ Wh,   const float* __restrict__ bhw,
    const float* __restrict__ Wf,   const float* __restrict__ bf,
    float* __restrict__ out, int out_size)
{
    extern __shared__ __align__(16) char smem_raw[];
    SM& sm = *reinterpret_cast<SM*>(smem_raw);
    const int blk = blockIdx.x;
    const int tid = threadIdx.x;
    const int lane = tid & 31, wid = tid >> 5;
    const int cg = lane, bg = wid;

    // ========== Stage 1: pos table (ALL blocks) + qw (blk<128) ==========
    {
        int idx0 = blk * NT_ + tid;
        int i = idx0 & 511;
        float freq = exp2f(-0.05190512648261504f * (float)(i >> 1));
        bool isOdd = (i & 1);
        for (int idx = idx0; idx < S_ * D_; idx += NB_ * NT_) {
            int t = idx >> 9;
            float ang = (float)t * freq;
            g_Pos[idx] = isOdd ? cosf(ang) : sinf(ang);
        }
    }
    if (blk < 128) {
        int b = blk >> 2, qt = blk & 3;
        int t0 = tok[b * S_];
        float v = emb[(size_t)t0 * D_ + tid] + (float)(tid & 1);
        sm.q.x0s[tid] = v;
        if (qt == 0) g_x0[b * D_ + tid] = v;
        __syncthreads();

        {   // q0 partials: thread = (d-quarter, h*32+e4). LDG.128 over e (coalesced).
            int quarter = tid >> 7;
            int g = tid & 127;
            int h = g >> 5;
            int e4 = g & 31;
            const float4* wrow =
                (const float4*)(Wp + ((size_t)h * D_ + quarter * 128) * DH_) + e4;
            const float* xq = sm.q.x0s + quarter * 128;
            float4 acc = make_float4(0.f, 0.f, 0.f, 0.f);
#pragma unroll 8
            for (int d = 0; d < 128; d++) {
                float4 wv = wrow[(size_t)d * (DH_ / 4)];
                float x = xq[d];
                acc.x += x * wv.x; acc.y += x * wv.y;
                acc.z += x * wv.z; acc.w += x * wv.w;
            }
            ((float4*)sm.q.q0p)[quarter * 128 + g] = acc;
        }
        __syncthreads();

        if (tid < 128) {
            const float4* p = (const float4*)sm.q.q0p;
            float4 a = p[tid], bq = p[128 + tid], cq = p[256 + tid], dq = p[384 + tid];
            int h = tid >> 5, e4 = tid & 31;
            float4 bias = *(const float4*)&bp[h * DH_ + e4 * 4];
            float4 q;
            q.x = bias.x + ((a.x + bq.x) + (cq.x + dq.x));
            q.y = bias.y + ((a.y + bq.y) + (cq.y + dq.y));
            q.z = bias.z + ((a.z + bq.z) + (cq.z + dq.z));
            q.w = bias.w + ((a.w + bq.w) + (cq.w + dq.w));
            ((float4*)sm.q.q0s)[tid] = q;
        }
        __syncthreads();

        if (qt == 0 && wid < 4) {   // c_h: warp h, warp-parallel dot
            float val = 0.f;
#pragma unroll
            for (int k = 0; k < 4; k++) {
                int e = lane + 32 * k;
                val += sm.q.q0s[wid * 128 + e] * bp[wid * DH_ + 128 + e];
            }
#pragma unroll
            for (int off = 16; off > 0; off >>= 1)
                val += __shfl_xor_sync(0xffffffff, val, off);
            if (lane == 0) g_c[b * H_ + wid] = val;
        }
        {   // w for head qt, d = tid
            const float4* wp4 = (const float4*)(Wp + ((size_t)qt * D_ + tid) * DH_ + 128);
            const float4* q4  = (const float4*)(sm.q.q0s + qt * 128);
            float acc = 0.f;
#pragma unroll
            for (int e4 = 0; e4 < 32; e4++) {
                float4 wv = wp4[e4], qv = q4[e4];
                acc += wv.x * qv.x + wv.y * qv.y + wv.z * qv.z + wv.w * qv.w;
            }
            g_w[b * (H_ * D_) + qt * D_ + tid] = acc;
        }
    }
    grid_bar();

    // ========== Stage C: pipelined gather + alpha + y (128 tiles, 1 sync/iter) ==========
    if (blk < B_ * NCH_) {
        const int b = blk & 31, chunk = blk >> 5;
        const float4* emb4 = (const float4*)emb;
        const float4* pos4 = (const float4*)g_Pos;

        // stage this chunk's 256 tokens into smem (read via LDS thereafter)
        if (tid < 256) sm.a.toks[tid] = tok[b * S_ + chunk * 256 + tid];

        // w cached in registers: wr[h][k] covers f4-group (lane + 32k)
        float4 wr[4][4];
        {
            const float4* gw4 = (const float4*)(g_w + b * (H_ * D_));
#pragma unroll
            for (int h = 0; h < 4; h++)
#pragma unroll
                for (int k = 0; k < 4; k++)
                    wr[h][k] = gw4[h * 128 + lane + 32 * k];
        }
        const float cs0 = g_c[b * H_ + 0];
        const float cs1 = g_c[b * H_ + 1];
        const float cs2 = g_c[b * H_ + 2];
        const float cs3 = g_c[b * H_ + 3];

        const int prow = tid >> 7, pc4 = tid & 127;
        float4 ev[4], pv[4];

        __syncthreads();   // toks visible

        {   // prologue: issue loads for subtile 0
#pragma unroll
            for (int r = 0; r < 4; r++) {
                int row = prow + r * 4;
                int tk = sm.a.toks[row];
                ev[r] = emb4[(size_t)tk * 128 + pc4];
                pv[r] = pos4[(size_t)(chunk * 256 + row) * 128 + pc4];
            }
        }

        float y0 = 0.f, y1 = 0.f, y2 = 0.f, y3 = 0.f;
        float aw0 = 0.f, aw1 = 0.f, aw2 = 0.f, aw3 = 0.f;

        for (int sub = 0; sub <= 16; sub++) {
            if (sub < 16) {
                float4* xst = (float4*)sm.a.xs[sub % 3];
#pragma unroll
                for (int r = 0; r < 4; r++) {
                    float4 vv;
                    vv.x = ev[r].x + pv[r].x; vv.y = ev[r].y + pv[r].y;
                    vv.z = ev[r].z + pv[r].z; vv.w = ev[r].w + pv[r].w;
                    xst[(prow + r * 4) * 128 + pc4] = vv;
                }
                if (sub < 15) {
                    int rl = (sub + 1) * 16;
#pragma unroll
                    for (int r = 0; r < 4; r++) {
                        int row = rl + prow + r * 4;
                        int tk = sm.a.toks[row];
                        ev[r] = emb4[(size_t)tk * 128 + pc4];
                        pv[r] = pos4[(size_t)(chunk * 256 + row) * 128 + pc4];
                    }
                }
            }
            __syncthreads();

            if (sub < 16) {
                const float4* xr = (const float4*)&sm.a.xs[sub % 3][wid][0];
                float s0 = 0.f, s1 = 0.f, s2 = 0.f, s3 = 0.f;
#pragma unroll
                for (int k = 0; k < 4; k++) {
                    float4 xv = xr[lane + 32 * k];
                    s0 += xv.x * wr[0][k].x + xv.y * wr[0][k].y
                        + xv.z * wr[0][k].z + xv.w * wr[0][k].w;
                    s1 += xv.x * wr[1][k].x + xv.y * wr[1][k].y
                        + xv.z * wr[1][k].z + xv.w * wr[1][k].w;
                    s2 += xv.x * wr[2][k].x + xv.y * wr[2][k].y
                        + xv.z * wr[2][k].z + xv.w * wr[2][k].w;
                    s3 += xv.x * wr[3][k].x + xv.y * wr[3][k].y
                        + xv.z * wr[3][k].z + xv.w * wr[3][k].w;
                }
#pragma unroll
                for (int off = 16; off > 0; off >>= 1) {
                    s0 += __shfl_xor_sync(0xffffffff, s0, off);
                    s1 += __shfl_xor_sync(0xffffffff, s1, off);
                    s2 += __shfl_xor_sync(0xffffffff, s2, off);
                    s3 += __shfl_xor_sync(0xffffffff, s3, off);
                }
                if (lane == 0) {
                    float a0 = s0 + cs0, a1 = s1 + cs1, a2 = s2 + cs2, a3 = s3 + cs3;
                    sm.a.al[sub & 1][wid][0] = a0;
                    sm.a.al[sub & 1][wid][1] = a1;
                    sm.a.al[sub & 1][wid][2] = a2;
                    sm.a.al[sub & 1][wid][3] = a3;
                    aw0 += a0; aw1 += a1; aw2 += a2; aw3 += a3;
                }
            }
            if (sub >= 1) {
                int ps = sub - 1;
                const float (*alp)[4] = sm.a.al[ps & 1];
                const float (*xsp)[512] = sm.a.xs[ps % 3];
#pragma unroll
                for (int tt = 0; tt < 16; tt++) {
                    float xv = xsp[tt][tid];
                    float4 a4 = *(const float4*)&alp[tt][0];
                    y0 += a4.x * xv;
                    y1 += a4.y * xv;
                    y2 += a4.z * xv;
                    y3 += a4.w * xv;
                }
            }
        }

        float* yp = g_ypart + ((size_t)(b * NCH_ + chunk)) * (H_ * D_);
        yp[0 * D_ + tid] = y0;
        yp[1 * D_ + tid] = y1;
        yp[2 * D_ + tid] = y2;
        yp[3 * D_ + tid] = y3;

        if (lane == 0) {
            sm.a.al[0][wid][0] = aw0;
            sm.a.al[0][wid][1] = aw1;
            sm.a.al[0][wid][2] = aw2;
            sm.a.al[0][wid][3] = aw3;
        }
        __syncthreads();
        if (tid < H_) {
            float a = 0.f;
#pragma unroll
            for (int w = 0; w < 16; w++) a += sm.a.al[0][w][tid];
            g_Apart[(b * NCH_ + chunk) * H_ + tid] = a;
        }
        __syncthreads();
    }
    grid_bar();

    // ========== F1: heads = y @ Wv + A*bv  (128 tiles of 64 cols) ==========
    GEMM_TILE64(
        /*stage*/ ({
            const int h_ = ct >> 1;
            float s = 0.f;
            _Pragma("unroll")
            for (int c = 0; c < NCH_; c++)
                s += g_ypart[((size_t)(bb * NCH_ + c)) * (H_ * D_) + h_ * D_ + kg];
            s; }),
        /*init*/ do {
            if (kb == 0) {
                const int h_ = ct >> 1;
                float4 bv = *(const float4*)&bp[h_ * DH_ + 256 + (ct & 1) * 64 + cg16 * 4];
                float av = 0.f;
                _Pragma("unroll")
                for (int c = 0; c < NCH_; c++) av += g_Apart[(bb1 * NCH_ + c) * H_ + h_];
                acc.x = av * bv.x; acc.y = av * bv.y;
                acc.z = av * bv.z; acc.w = av * bv.w;
            } else acc = make_float4(0.f, 0.f, 0.f, 0.f);
        } while (0),
        /*W*/ (Wp + ((size_t)(ct >> 1) * D_ + kg) * DH_ + 256 + (ct & 1) * 64 + cg16 * 4),
        /*out*/ do { *(float4*)&g_hp[kb][bb1 * D_ + col] = acc; } while (0));
    grid_bar();

    // ========== F2: x1 = scale*heads @ Wo + bo + x0  (128 tiles) ==========
    GEMM_TILE64(
        /*stage*/ ({
            float s = 0.f;
            _Pragma("unroll")
            for (int p = 0; p < 16; p++) s += g_hp[p][bb * D_ + kg];
            s * 0.03125f; }),
        /*init*/ do {
            if (kb == 0) {
                float4 bv = *(const float4*)&bo[col];
                float4 xv = *(const float4*)&g_x0[bb1 * D_ + col];
                acc.x = bv.x + xv.x; acc.y = bv.y + xv.y;
                acc.z = bv.z + xv.z; acc.w = bv.w + xv.w;
            } else acc = make_float4(0.f, 0.f, 0.f, 0.f);
        } while (0),
        /*W*/ (Wo + (size_t)kg * D_ + col),
        /*out*/ do { *(float4*)&g_x1p[kb][bb1 * D_ + col] = acc; } while (0));
    grid_bar();

    // ========== LN1 ==========
    if (blk < B_) {
        int b = blk;
        float v = 0.f;
#pragma unroll
        for (int p = 0; p < 16; p++) v += g_x1p[p][b * D_ + tid];
        float mu  = redsum(v, sm.r.red) * (1.f / D_);
        float dv  = v - mu;
        float var = redsum(dv * dv, sm.r.red) * (1.f / D_);
        g_x1n[b * D_ + tid] = dv * rsqrtf(var + 1e-3f) * g1[tid] + bln1[tid];
    }
    grid_bar();

    // ========== F3: h1 = x1n @ W1 + b1  (128 tiles) ==========
    GEMM_TILE(16, 8,
        /*stage*/ (g_x1n[bb * D_ + kg]),
        /*init*/ do {
            if (kb == 0) {
                float4 bv = *(const float4*)&b1[col];
                acc[0] = bv; acc[1] = bv;
            } else ACC_ZERO();
        } while (0),
        /*W*/ (W1 + (size_t)kg * FFN_ + col),
        /*out*/ do {
            _Pragma("unroll")
            for (int j = 0; j < 2; j++)
                *(float4*)&g_h1p[kb][(bg * 2 + j) * FFN_ + col] = acc[j];
        } while (0));
    grid_bar();

    // ========== F4: x2 = relu(h1) @ W2 + b2 + x1n  (128 tiles) ==========
    GEMM_TILE(4, 32,
        /*stage*/ ({
            float s = 0.f;
            _Pragma("unroll")
            for (int p = 0; p < 8; p++) s += g_h1p[p][bb * FFN_ + kg];
            fmaxf(s, 0.f); }),
        /*init*/ do {
            if (kb == 0) {
                float4 bv = *(const float4*)&b2[col];
                _Pragma("unroll")
                for (int j = 0; j < 2; j++) {
                    float4 xv = *(const float4*)&g_x1n[(bg * 2 + j) * D_ + col];
                    acc[j].x = bv.x + xv.x; acc[j].y = bv.y + xv.y;
                    acc[j].z = bv.z + xv.z; acc[j].w = bv.w + xv.w;
                }
            } else ACC_ZERO();
        } while (0),
        /*W*/ (W2 + (size_t)kg * D_ + col),
        /*out*/ do {
            _Pragma("unroll")
            for (int j = 0; j < 2; j++)
                *(float4*)&g_x2p[kb][(bg * 2 + j) * D_ + col] = acc[j];
        } while (0));
    grid_bar();

    // ========== LN2 ==========
    if (blk < B_) {
        int b = blk;
        float v = 0.f;
#pragma unroll
        for (int p = 0; p < 32; p++) v += g_x2p[p][b * D_ + tid];
        float mu  = redsum(v, sm.r.red) * (1.f / D_);
        float dv  = v - mu;
        float var = redsum(dv * dv, sm.r.red) * (1.f / D_);
        g_x2[b * D_ + tid] = dv * rsqrtf(var + 1e-3f) * g2[tid] + bln2[tid];
    }
    grid_bar();

    // ========== F5: hid = x2 @ Wh + bh  (128 tiles) ==========
    GEMM_TILE64(
        /*stage*/ (g_x2[bb * D_ + kg]),
        /*init*/ do {
            if (kb == 0) {
                acc = *(const float4*)&bhw[col];
            } else acc = make_float4(0.f, 0.f, 0.f, 0.f);
        } while (0),
        /*W*/ (Wh + (size_t)kg * D_ + col),
        /*out*/ do { *(float4*)&g_hidp[kb][bb1 * D_ + col] = acc; } while (0));
    grid_bar();

    // ========== logits ==========
    if (blk < B_) {
        int b = blk;
        float v = 0.f;
#pragma unroll
        for (int p = 0; p < 16; p++) v += g_hidp[p][b * D_ + tid];
        float hid = fmaxf(v, 0.f);
        float s = redsum(hid * Wf[tid], sm.r.red);
        if (tid == 0) {
            float logit = s + bf[0];
            if (b < out_size)      out[b]      = logit;
            if (B_ + b < out_size) out[B_ + b] = 1.f / (1.f + expf(-logit));
        }
    }
}

// ---------------------------------------------------------------------------
extern "C" void kernel_launch(void* const* d_in, const int* in_sizes, int n_in,
                              void* d_out, int out_size) {
    const int*   inputs = (const int*)  d_in[0];
    const float* emb    = (const float*)d_in[1];
    const float* Wp     = (const float*)d_in[2];
    const float* bp     = (const float*)d_in[3];
    const float* Wo     = (const float*)d_in[4];
    const float* bo     = (const float*)d_in[5];
    const float* ln1g   = (const float*)d_in[6];
    const float* ln1b   = (const float*)d_in[7];
    const float* W1     = (const float*)d_in[8];
    const float* b1     = (const float*)d_in[9];
    const float* W2     = (const float*)d_in[10];
    const float* b2     = (const float*)d_in[11];
    const float* ln2g   = (const float*)d_in[12];
    const float* ln2b   = (const float*)d_in[13];
    const float* Wh     = (const float*)d_in[14];
    const float* bhp    = (const float*)d_in[15];
    const float* Wf     = (const float*)d_in[16];
    const float* bf     = (const float*)d_in[17];
    float* out = (float*)d_out;

    static_assert(sizeof(SM) < 200 * 1024, "smem budget");
    cudaFuncSetAttribute(mega_kernel,
                         cudaFuncAttributeMaxDynamicSharedMemorySize,
                         (int)sizeof(SM));
    mega_kernel<<<NB_, NT_, sizeof(SM)>>>(inputs, emb, Wp, bp, Wo, bo,
                                          ln1g, ln1b, W1, b1, W2, b2,
                                          ln2g, ln2b, Wh, bhp, Wf, bf,
                                          out, out_size);
}